// round 1
// baseline (speedup 1.0000x reference)
#include <cuda_runtime.h>
#include <math.h>

// Router: logits = x @ W^T + b ; softmax ; top-2 ; renormalize.
// x: [T, D] f32, W: [E, D] f32, b: [E] f32.
// Output layout assumption (tuple flattened in order):
//   out[0 : 2T)      = top-2 indices as float, row-major [T, 2]
//   out[2T : 4T)     = renormalized top-2 probs, row-major [T, 2]

#define BM 128   // tokens per CTA
#define BK 16    // k-chunk
#define NE 128   // experts (all resident)

__global__ __launch_bounds__(256, 1)
void router_kernel(const float* __restrict__ x,
                   const float* __restrict__ W,
                   const float* __restrict__ bias,
                   float* __restrict__ out,
                   int T, int D, int E)
{
    extern __shared__ float sm[];
    float* xs = sm;              // [BK][BM] transposed x tile
    float* ws = sm + BK * BM;    // [BK][NE] transposed W tile

    const int tid = threadIdx.x;
    const int tx  = tid & 15;    // expert-group  (experts tx*8 .. tx*8+7)
    const int ty  = tid >> 4;    // token-group   (tokens  ty*8 .. ty*8+7)
    const int t0  = blockIdx.x * BM;

    float acc[8][8];
#pragma unroll
    for (int i = 0; i < 8; i++)
#pragma unroll
        for (int j = 0; j < 8; j++) acc[i][j] = 0.0f;

    for (int k0 = 0; k0 < D; k0 += BK) {
        // Cooperative load: 128 rows x 16 cols for both x and W,
        // 512 float4 each, 2 per thread, stored transposed into smem.
#pragma unroll
        for (int l = 0; l < 2; l++) {
            int f   = tid + l * 256;   // 0..511
            int row = f >> 2;          // 0..127 (token or expert)
            int c4  = f & 3;           // which float4 within the 16-wide chunk
            float4 vx = *reinterpret_cast<const float4*>(
                &x[(size_t)(t0 + row) * D + k0 + c4 * 4]);
            xs[(c4 * 4 + 0) * BM + row] = vx.x;
            xs[(c4 * 4 + 1) * BM + row] = vx.y;
            xs[(c4 * 4 + 2) * BM + row] = vx.z;
            xs[(c4 * 4 + 3) * BM + row] = vx.w;
            float4 vw = *reinterpret_cast<const float4*>(
                &W[(size_t)row * D + k0 + c4 * 4]);
            ws[(c4 * 4 + 0) * NE + row] = vw.x;
            ws[(c4 * 4 + 1) * NE + row] = vw.y;
            ws[(c4 * 4 + 2) * NE + row] = vw.z;
            ws[(c4 * 4 + 3) * NE + row] = vw.w;
        }
        __syncthreads();

#pragma unroll
        for (int kk = 0; kk < BK; kk++) {
            float4 a0 = *reinterpret_cast<const float4*>(&xs[kk * BM + ty * 8]);
            float4 a1 = *reinterpret_cast<const float4*>(&xs[kk * BM + ty * 8 + 4]);
            float4 b0 = *reinterpret_cast<const float4*>(&ws[kk * NE + tx * 8]);
            float4 b1 = *reinterpret_cast<const float4*>(&ws[kk * NE + tx * 8 + 4]);
            float xf[8] = {a0.x, a0.y, a0.z, a0.w, a1.x, a1.y, a1.z, a1.w};
            float wf[8] = {b0.x, b0.y, b0.z, b0.w, b1.x, b1.y, b1.z, b1.w};
#pragma unroll
            for (int i = 0; i < 8; i++)
#pragma unroll
                for (int j = 0; j < 8; j++)
                    acc[i][j] = fmaf(xf[i], wf[j], acc[i][j]);
        }
        __syncthreads();
    }

    // ---- Epilogue: stash logits (+bias) in smem, pitch 129 (conflict-free scans)
    float* logits = sm;  // reuse: 128 * 129 floats = 66048 B
#pragma unroll
    for (int i = 0; i < 8; i++)
#pragma unroll
        for (int j = 0; j < 8; j++)
            logits[(ty * 8 + i) * 129 + (tx * 8 + j)] = acc[i][j] + bias[tx * 8 + j];
    __syncthreads();

    if (tid < BM) {
        const float* row = &logits[tid * 129];
        // pass 1: max
        float m = row[0];
#pragma unroll 4
        for (int e = 1; e < NE; e++) m = fmaxf(m, row[e]);
        // pass 2: sumexp + top-2 (strict > keeps earliest index, matching lax.top_k)
        float s = 0.0f;
        float v1 = -INFINITY, v2 = -INFINITY;
        int   i1 = 0, i2 = 0;
#pragma unroll 4
        for (int e = 0; e < NE; e++) {
            float v = row[e];
            s += __expf(v - m);
            if (v > v1)      { v2 = v1; i2 = i1; v1 = v; i1 = e; }
            else if (v > v2) { v2 = v;  i2 = e; }
        }
        float e1 = __expf(v1 - m), e2 = __expf(v2 - m);
        float p1 = e1 / s, p2 = e2 / s;
        float den = p1 + p2 + 1e-8f;
        int t = t0 + tid;
        out[(size_t)t * 2 + 0] = (float)i1;
        out[(size_t)t * 2 + 1] = (float)i2;
        out[(size_t)2 * T + t * 2 + 0] = p1 / den;
        out[(size_t)2 * T + t * 2 + 1] = p2 / den;
    }
}

extern "C" void kernel_launch(void* const* d_in, const int* in_sizes, int n_in,
                              void* d_out, int out_size)
{
    const float* x = (const float*)d_in[0];
    const float* W = (const float*)d_in[1];
    const float* b = (const float*)d_in[2];
    float* out = (float*)d_out;

    int E = in_sizes[2];              // 128
    int D = in_sizes[1] / E;          // 4096
    int T = in_sizes[0] / D;          // 16384

    const int smem_bytes = 128 * 129 * sizeof(float);  // 66048 (> tiles' 16KB)
    cudaFuncSetAttribute(router_kernel,
                         cudaFuncAttributeMaxDynamicSharedMemorySize, smem_bytes);

    router_kernel<<<T / BM, 256, smem_bytes>>>(x, W, b, out, T, D, E);
}

// round 3
// speedup vs baseline: 2.8686x; 2.8686x over previous
#include <cuda_runtime.h>
#include <cuda_fp16.h>
#include <cstdint>
#include <math.h>

// logits = x @ W^T + b ; softmax ; top-2 ; renormalize.
// GEMM via mma.sync m16n8k16 fp16 with exact 2-term split (hh + hl + lh),
// fp32 accumulate. W scaled by 64 to dodge fp16 subnormals, undone in epilogue.
// out[0:2T) = indices (as f32), out[2T:4T) = renormalized probs.

static constexpr int D_K  = 4096;
static constexpr int NE   = 128;    // experts
static constexpr int BM   = 128;    // tokens per CTA
static constexpr int KC   = 32;     // K per chunk
static constexpr int NCH  = D_K / KC;      // 128
static constexpr int RS   = 40;            // halves per smem row (32 + 8 pad)
static constexpr int TILE_B  = BM * RS * 2;   // 10240 B per half-tile
static constexpr int STAGE_B = 4 * TILE_B;    // A_hi, A_lo, B_hi, B_lo = 40960 B
static constexpr int SMEM_TOTAL = 2 * STAGE_B; // 81920 B (epilogue reuses: 66048 B)
static constexpr float WSCALE  = 64.0f;
static constexpr float IWSCALE = 1.0f / 64.0f;

__device__ __forceinline__ uint32_t smem_u32(const void* p) {
    uint32_t a;
    asm("{ .reg .u64 t; cvta.to.shared.u64 t, %1; cvt.u32.u64 %0, t; }" : "=r"(a) : "l"(p));
    return a;
}

#define LDM4(r, addr)                                                        \
    asm volatile("ldmatrix.sync.aligned.m8n8.x4.shared.b16 {%0,%1,%2,%3}, [%4];" \
                 : "=r"((r)[0]), "=r"((r)[1]), "=r"((r)[2]), "=r"((r)[3])    \
                 : "r"(addr))

#define MMA16816(c, a, b0, b1)                                               \
    asm volatile("mma.sync.aligned.m16n8k16.row.col.f32.f16.f16.f32 "        \
                 "{%0,%1,%2,%3}, {%4,%5,%6,%7}, {%8,%9}, {%0,%1,%2,%3};"     \
                 : "+f"((c)[0]), "+f"((c)[1]), "+f"((c)[2]), "+f"((c)[3])    \
                 : "r"((a)[0]), "r"((a)[1]), "r"((a)[2]), "r"((a)[3]),       \
                   "r"(b0), "r"(b1))

__device__ __forceinline__ uint32_t pack_hi(float a, float b, float& la, float& lb) {
    __half ha = __float2half_rn(a);
    __half hb = __float2half_rn(b);
    la = a - __half2float(ha);
    lb = b - __half2float(hb);
    __half2 h = __halves2half2(ha, hb);
    return *reinterpret_cast<uint32_t*>(&h);
}
__device__ __forceinline__ uint32_t pack_lo(float a, float b) {
    __half2 h = __floats2half2_rn(a, b);
    return *reinterpret_cast<uint32_t*>(&h);
}

__global__ void __launch_bounds__(512, 1)
router_mma(const float* __restrict__ x, const float* __restrict__ W,
           const float* __restrict__ bias, float* __restrict__ out, int T)
{
    extern __shared__ char smem[];
    const uint32_t sbase = smem_u32(smem);
    const int tid  = threadIdx.x;
    const int wid  = tid >> 5, lane = tid & 31;
    const int wm   = wid & 3;        // warp row  (32 tokens)
    const int wn   = wid >> 2;       // warp col  (32 experts)
    const int t0   = blockIdx.x * BM;

    float acc[2][4][4];
#pragma unroll
    for (int i = 0; i < 2; i++)
#pragma unroll
        for (int j = 0; j < 4; j++)
#pragma unroll
            for (int k = 0; k < 4; k++) acc[i][j][k] = 0.0f;

    // ldmatrix per-lane offset (halves) within a 16x16 block:
    // tile = lane>>3 : t0=(r0-7,k0-7) t1=(r8-15,k0-7) t2=(r0-7,k8-15) t3=(r8-15,k8-15)
    const int ltile = lane >> 3, lr = lane & 7;
    const int lmoff = ((ltile & 1) * 8 + lr) * RS + (ltile >> 1) * 8;

    // LDG slices: 1024 float4 per 128x32 f32 tile -> 2 per thread (i = tid, tid+512)
    float4 av[2], wv[2];
#pragma unroll
    for (int j = 0; j < 2; j++) {
        int i = tid + j * 512, row = i >> 3, c4 = i & 7;
        av[j] = *reinterpret_cast<const float4*>(x + (size_t)(t0 + row) * D_K + c4 * 4);
        wv[j] = *reinterpret_cast<const float4*>(W + (size_t)row * D_K + c4 * 4);
    }

    for (int c = 0; c < NCH; c++) {
        const int s = c & 1;

        // ---- STS current chunk (convert to hi/lo fp16) ----
        {
            char* base = smem + s * STAGE_B;
#pragma unroll
            for (int j = 0; j < 2; j++) {
                int i = tid + j * 512, row = i >> 3, c4 = i & 7;
                uint32_t off = (uint32_t)(row * RS + c4 * 4) * 2;  // bytes
                float lx, ly, lz, lw;
                uint2 hi, lo;
                hi.x = pack_hi(av[j].x, av[j].y, lx, ly);
                hi.y = pack_hi(av[j].z, av[j].w, lz, lw);
                lo.x = pack_lo(lx, ly); lo.y = pack_lo(lz, lw);
                *reinterpret_cast<uint2*>(base + off)          = hi;
                *reinterpret_cast<uint2*>(base + TILE_B + off) = lo;
                float bx = wv[j].x * WSCALE, by = wv[j].y * WSCALE;
                float bz = wv[j].z * WSCALE, bw = wv[j].w * WSCALE;
                hi.x = pack_hi(bx, by, lx, ly);
                hi.y = pack_hi(bz, bw, lz, lw);
                lo.x = pack_lo(lx, ly); lo.y = pack_lo(lz, lw);
                *reinterpret_cast<uint2*>(base + 2 * TILE_B + off) = hi;
                *reinterpret_cast<uint2*>(base + 3 * TILE_B + off) = lo;
            }
        }

        // ---- prefetch next chunk into registers ----
        if (c + 1 < NCH) {
            const int k0 = (c + 1) * KC;
#pragma unroll
            for (int j = 0; j < 2; j++) {
                int i = tid + j * 512, row = i >> 3, c4 = i & 7;
                av[j] = *reinterpret_cast<const float4*>(
                    x + (size_t)(t0 + row) * D_K + k0 + c4 * 4);
                wv[j] = *reinterpret_cast<const float4*>(
                    W + (size_t)row * D_K + k0 + c4 * 4);
            }
        }
        __syncthreads();

        // ---- compute on this stage ----
        {
            const uint32_t aHi = sbase + s * STAGE_B;
            const uint32_t aLo = aHi + TILE_B;
            const uint32_t bHi = aHi + 2 * TILE_B;
            const uint32_t bLo = aHi + 3 * TILE_B;
#pragma unroll
            for (int kk = 0; kk < 2; kk++) {   // two k16 steps
                uint32_t Ah[2][4], Al[2][4], Bh[2][4], Bl[2][4];
#pragma unroll
                for (int mt = 0; mt < 2; mt++) {
                    uint32_t off = (uint32_t)((wm * 32 + mt * 16) * RS + kk * 16 + lmoff) * 2;
                    LDM4(Ah[mt], aHi + off);
                    LDM4(Al[mt], aLo + off);
                }
#pragma unroll
                for (int g = 0; g < 2; g++) {
                    uint32_t off = (uint32_t)((wn * 32 + g * 16) * RS + kk * 16 + lmoff) * 2;
                    LDM4(Bh[g], bHi + off);
                    LDM4(Bl[g], bLo + off);
                }
#pragma unroll
                for (int mt = 0; mt < 2; mt++) {
#pragma unroll
                    for (int nt = 0; nt < 4; nt++) {
                        const int g = nt >> 1, r0 = nt & 1;
                        MMA16816(acc[mt][nt], Ah[mt], Bh[g][r0], Bh[g][r0 + 2]);
                        MMA16816(acc[mt][nt], Ah[mt], Bl[g][r0], Bl[g][r0 + 2]);
                        MMA16816(acc[mt][nt], Al[mt], Bh[g][r0], Bh[g][r0 + 2]);
                    }
                }
            }
        }
        __syncthreads();
    }

    // ---- epilogue: logits to smem (pitch 129), then per-token top-2 ----
    float* lg = reinterpret_cast<float*>(smem);
    const int lr4 = lane >> 2, lc2 = (lane & 3) * 2;
#pragma unroll
    for (int mt = 0; mt < 2; mt++)
#pragma unroll
        for (int nt = 0; nt < 4; nt++)
#pragma unroll
            for (int di = 0; di < 4; di++) {
                int row = wm * 32 + mt * 16 + lr4 + (di >> 1) * 8;
                int col = wn * 32 + nt * 8 + lc2 + (di & 1);
                lg[row * 129 + col] = acc[mt][nt][di] * IWSCALE + __ldg(&bias[col]);
            }
    __syncthreads();

    if (tid < BM) {
        const float* row = &lg[tid * 129];
        float v1 = -INFINITY, v2 = -INFINITY;
        int   i1 = 0, i2 = 0;
#pragma unroll 4
        for (int e = 0; e < NE; e++) {
            float v = row[e];
            if (v > v1)      { v2 = v1; i2 = i1; v1 = v; i1 = e; }
            else if (v > v2) { v2 = v;  i2 = e; }
        }
        float ssum = 0.0f;
#pragma unroll 4
        for (int e = 0; e < NE; e++) ssum += __expf(row[e] - v1);
        float p1 = 1.0f / ssum;
        float p2 = __expf(v2 - v1) / ssum;
        float den = p1 + p2 + 1e-8f;
        int t = t0 + tid;
        out[(size_t)t * 2 + 0] = (float)i1;
        out[(size_t)t * 2 + 1] = (float)i2;
        out[(size_t)2 * T + (size_t)t * 2 + 0] = p1 / den;
        out[(size_t)2 * T + (size_t)t * 2 + 1] = p2 / den;
    }
}

extern "C" void kernel_launch(void* const* d_in, const int* in_sizes, int n_in,
                              void* d_out, int out_size)
{
    const float* x = (const float*)d_in[0];
    const float* W = (const float*)d_in[1];
    const float* b = (const float*)d_in[2];
    float* out = (float*)d_out;

    int E = in_sizes[2];            // 128
    int D = in_sizes[1] / E;        // 4096
    int T = in_sizes[0] / D;        // 16384

    static int configured = -1;
    if (configured < 0) {
        cudaFuncSetAttribute(router_mma, cudaFuncAttributeMaxDynamicSharedMemorySize,
                             SMEM_TOTAL);
        configured = 1;
    }
    router_mma<<<T / BM, 512, SMEM_TOTAL>>>(x, W, b, out, T);
}